// round 6
// baseline (speedup 1.0000x reference)
#include <cuda_runtime.h>
#include <cuda_fp16.h>
#include <cstdint>

// Problem constants
#define BATCH   16384
#define NCLS    1000
#define NPAD    1024
#define KDIM    1024

// GEMM tiling (fp16): CTA 128x256, 8 warps in 2(M) x 4(N), warp tile 64x64
#define BM 128
#define BN 256
#define BKH 64               // halves per k-chunk (128 bytes per smem row)
#define KT (KDIM / BKH)      // 16 k-chunks
#define NT 4                 // 4 * 256 = 1024 >= 1000
#define SLD 36               // smem row stride in uint32 (32 data + 4 pad)

// ---------------------------------------------------------------------------
// Scratch (zero-initialized; pad rows of g_ch stay zero forever)
// ---------------------------------------------------------------------------
__device__ __half g_xh[(size_t)BATCH * KDIM];    // fp16 x
__device__ __half g_ch[(size_t)NPAD * KDIM];     // fp16 centers, rows 1000..1023 zero
__device__ float  g_c2[NPAD];                    // exact fp32 ||c||^2
__device__ float  g_pos[BATCH];
__device__ float  g_minxc[(size_t)BATCH * NT];
__device__ float  g_mincc[(size_t)NPAD * NT];
__device__ float  g_cen[NPAD];
__device__ float  g_part[64];

// ---------------------------------------------------------------------------
// Prep: fp32 -> fp16 (RN). Device symbols referenced only in device code.
// ---------------------------------------------------------------------------
__device__ __forceinline__ uint2 cvt4(float4 v) {
    __half2 lo = __floats2half2_rn(v.x, v.y);
    __half2 hi = __floats2half2_rn(v.z, v.w);
    uint2 o;
    o.x = *reinterpret_cast<uint32_t*>(&lo);
    o.y = *reinterpret_cast<uint32_t*>(&hi);
    return o;
}

__global__ void conv_x_kernel(const float* __restrict__ src, int n4) {
    int i = blockIdx.x * blockDim.x + threadIdx.x;
    if (i < n4)
        reinterpret_cast<uint2*>(g_xh)[i] = cvt4(reinterpret_cast<const float4*>(src)[i]);
}

__global__ void conv_c_kernel(const float* __restrict__ src, int n4) {
    int i = blockIdx.x * blockDim.x + threadIdx.x;
    if (i < n4)
        reinterpret_cast<uint2*>(g_ch)[i] = cvt4(reinterpret_cast<const float4*>(src)[i]);
}

// Exact fp32 squared norms of centers
__global__ void c2_kernel(const float* __restrict__ centers) {
    int j = blockIdx.x;
    const float* row = centers + (size_t)j * KDIM;
    float acc = 0.f;
    for (int k = threadIdx.x; k < KDIM; k += 256) {
        float v = row[k];
        acc += v * v;
    }
    __shared__ float s[256];
    s[threadIdx.x] = acc;
    __syncthreads();
    for (int off = 128; off > 0; off >>= 1) {
        if (threadIdx.x < off) s[threadIdx.x] += s[threadIdx.x + off];
        __syncthreads();
    }
    if (threadIdx.x == 0) g_c2[j] = s[0];
}

// ---------------------------------------------------------------------------
// fp16 GEMM + fused min epilogue
// e[r,c] = 0.5*||c_c||^2 - dot(A_r, C_c)
// SELF=false: A = g_xh; exclude c == label[r]; write g_pos, g_minxc
// SELF=true:  A = g_ch; exclude c == r;        write g_mincc
// ---------------------------------------------------------------------------
template <int ROWS>
__device__ __forceinline__ void cp_tile(const __half* gbase, uint32_t* sbase, int tid) {
#pragma unroll
    for (int i = 0; i < ROWS * 8 / 256; i++) {
        int g = i * 256 + tid;          // chunk id
        int r = g >> 3;                 // row
        int q = g & 7;                  // 16B chunk within row
        uint32_t d = (uint32_t)__cvta_generic_to_shared(sbase + r * SLD + q * 4);
        const __half* s = gbase + (size_t)r * KDIM + q * 8;
        asm volatile("cp.async.cg.shared.global [%0], [%1], 16;" :: "r"(d), "l"(s));
    }
}

template <bool SELF>
__global__ void __launch_bounds__(256, 1)
gemm_min_kernel(const int* __restrict__ labels) {
    extern __shared__ uint32_t smem[];
    uint32_t* As  = smem;                          // 2 * 128 * 36 u32
    uint32_t* Bs  = smem + 2 * BM * SLD;           // 2 * 256 * 36 u32
    float*    c2s = (float*)(Bs + 2 * BN * SLD);   // 256 floats (pre-scaled by 0.5)
    float*    red = c2s + 256;                     // 128 * 4 floats
    int*      labs = (int*)(red + 512);            // 128 ints

    const int tid  = threadIdx.x;
    const int warp = tid >> 5;
    const int lane = tid & 31;
    const int wm   = warp >> 2;   // 0..1 (M warps, 64 rows each)
    const int wn   = warp & 3;    // 0..3 (N warps, 64 cols each)
    const int bx   = blockIdx.x;  // n-tile 0..3
    const int m0   = blockIdx.y * BM;
    const int n0   = bx * BN;

    const __half* A = SELF ? g_ch : g_xh;

    c2s[tid] = 0.5f * g_c2[n0 + tid];
    if (!SELF && tid < 128) labs[tid] = labels[m0 + tid];

    float acc[4][8][4];
#pragma unroll
    for (int mi = 0; mi < 4; mi++)
#pragma unroll
        for (int ni = 0; ni < 8; ni++)
#pragma unroll
            for (int r = 0; r < 4; r++) acc[mi][ni][r] = 0.f;

    const __half* Abase = A + (size_t)m0 * KDIM;
    const __half* Bbase = g_ch + (size_t)n0 * KDIM;

    // prologue: stage 0
    cp_tile<BM>(Abase, As, tid);
    cp_tile<BN>(Bbase, Bs, tid);
    asm volatile("cp.async.commit_group;");

    const int lr = lane >> 2, lc = lane & 3;

    for (int kt = 0; kt < KT; kt++) {
        if (kt + 1 < KT) {
            int st = (kt + 1) & 1;
            cp_tile<BM>(Abase + (size_t)(kt + 1) * BKH, As + st * BM * SLD, tid);
            cp_tile<BN>(Bbase + (size_t)(kt + 1) * BKH, Bs + st * BN * SLD, tid);
            asm volatile("cp.async.commit_group;");
            asm volatile("cp.async.wait_group 1;");
        } else {
            asm volatile("cp.async.wait_group 0;");
        }
        __syncthreads();

        const uint32_t* a_s = As + (kt & 1) * BM * SLD;
        const uint32_t* b_s = Bs + (kt & 1) * BN * SLD;

#pragma unroll
        for (int kk = 0; kk < 4; kk++) {
            // proven round-5 fragment indexing; elements are half2
            uint32_t af[4][4], bf[8][2];
#pragma unroll
            for (int mi = 0; mi < 4; mi++) {
                const uint32_t* p = a_s + (wm * 64 + mi * 16 + lr) * SLD + kk * 8 + lc;
                af[mi][0] = p[0];            // a0: (row lr,    k 2lc..2lc+1)
                af[mi][2] = p[4];            // a2: (row lr,    k 2lc+8..9)
                af[mi][1] = p[8 * SLD];      // a1: (row lr+8,  k 2lc..2lc+1)
                af[mi][3] = p[8 * SLD + 4];  // a3: (row lr+8,  k 2lc+8..9)
            }
#pragma unroll
            for (int ni = 0; ni < 8; ni++) {
                const uint32_t* p = b_s + (wn * 64 + ni * 8 + lr) * SLD + kk * 8 + lc;
                bf[ni][0] = p[0];            // b0: (k 2lc..2lc+1, n lr)
                bf[ni][1] = p[4];            // b1: (k 2lc+8..9,   n lr)
            }
#pragma unroll
            for (int mi = 0; mi < 4; mi++)
#pragma unroll
                for (int ni = 0; ni < 8; ni++) {
                    asm volatile(
                        "mma.sync.aligned.m16n8k16.row.col.f32.f16.f16.f32 "
                        "{%0,%1,%2,%3}, {%4,%5,%6,%7}, {%8,%9}, {%0,%1,%2,%3};"
                        : "+f"(acc[mi][ni][0]), "+f"(acc[mi][ni][1]),
                          "+f"(acc[mi][ni][2]), "+f"(acc[mi][ni][3])
                        : "r"(af[mi][0]), "r"(af[mi][1]), "r"(af[mi][2]), "r"(af[mi][3]),
                          "r"(bf[ni][0]), "r"(bf[ni][1]));
                }
        }
        __syncthreads();
    }

    // ---------------- fused epilogue ----------------
    const float INF = __int_as_float(0x7f800000);
    float rmin[4][2];

#pragma unroll
    for (int mi = 0; mi < 4; mi++)
#pragma unroll
        for (int h = 0; h < 2; h++) {
            int rloc = wm * 64 + mi * 16 + lr + 8 * h;
            float rm = INF;
#pragma unroll
            for (int ni = 0; ni < 8; ni++)
#pragma unroll
                for (int cc = 0; cc < 2; cc++) {
                    int cloc = wn * 64 + ni * 8 + lc * 2 + cc;
                    float e = c2s[cloc] - acc[mi][ni][h * 2 + cc];
                    int cg = n0 + cloc;
                    bool excl = (cg >= NCLS);
                    if (SELF) {
                        excl = excl || (cg == m0 + rloc);
                    } else if (cg == labs[rloc]) {
                        g_pos[m0 + rloc] = e;
                        excl = true;
                    }
                    if (!excl) rm = fminf(rm, e);
                }
            rmin[mi][h] = rm;
        }

#pragma unroll
    for (int mi = 0; mi < 4; mi++)
#pragma unroll
        for (int h = 0; h < 2; h++) {
            float v = rmin[mi][h];
            v = fminf(v, __shfl_xor_sync(0xffffffffu, v, 1));
            v = fminf(v, __shfl_xor_sync(0xffffffffu, v, 2));
            rmin[mi][h] = v;
        }

    if (lc == 0) {
#pragma unroll
        for (int mi = 0; mi < 4; mi++)
#pragma unroll
            for (int h = 0; h < 2; h++) {
                int rloc = wm * 64 + mi * 16 + lr + 8 * h;
                red[rloc * 4 + wn] = rmin[mi][h];
            }
    }
    __syncthreads();

    if (tid < 128) {
        float v = fminf(fminf(red[tid * 4], red[tid * 4 + 1]),
                        fminf(red[tid * 4 + 2], red[tid * 4 + 3]));
        int rg = m0 + tid;
        if (SELF) {
            if (rg < NCLS) g_mincc[(size_t)rg * NT + bx] = v;
        } else {
            g_minxc[(size_t)rg * NT + bx] = v;
        }
    }
}

// ---------------------------------------------------------------------------
// Deterministic reduction chain (NT = 4 -> one float4 per row)
// ---------------------------------------------------------------------------
__global__ void cen_kernel() {
    int j = blockIdx.x * blockDim.x + threadIdx.x;
    if (j < NCLS) {
        float4 a = reinterpret_cast<const float4*>(g_mincc)[j];
        float m = fminf(fminf(a.x, a.y), fminf(a.z, a.w));
        g_cen[j] = 0.5f * g_c2[j] + m;
    }
}

__global__ void partial_kernel(const int* __restrict__ labels) {
    int b = blockIdx.x * 256 + threadIdx.x;
    float4 a = reinterpret_cast<const float4*>(g_minxc)[b];
    float m = fminf(fminf(a.x, a.y), fminf(a.z, a.w));
    float t1 = g_pos[b] + 5.0f - m;     // 0.5||x||^2 cancels in pos - neg
    float t2 = 7.0f - g_cen[labels[b]];
    float v = fmaxf(t1, 0.f) + fmaxf(t2, 0.f);
    __shared__ float s[256];
    s[threadIdx.x] = v;
    __syncthreads();
    for (int off = 128; off > 0; off >>= 1) {
        if (threadIdx.x < off) s[threadIdx.x] += s[threadIdx.x + off];
        __syncthreads();
    }
    if (threadIdx.x == 0) g_part[blockIdx.x] = s[0];
}

__global__ void finish_kernel(float* __restrict__ out) {
    int t = threadIdx.x;   // 32 threads
    float v = g_part[t] + g_part[t + 32];
#pragma unroll
    for (int off = 16; off > 0; off >>= 1)
        v += __shfl_xor_sync(0xffffffffu, v, off);
    if (t == 0) out[0] = v * (1.0f / (float)BATCH);
}

// ---------------------------------------------------------------------------
// Launch
// ---------------------------------------------------------------------------
extern "C" void kernel_launch(void* const* d_in, const int* in_sizes, int n_in,
                              void* d_out, int out_size) {
    const float* x       = (const float*)d_in[0];
    const int*   labels  = (const int*)d_in[1];
    const float* centers = (const float*)d_in[2];
    float* out = (float*)d_out;

    const int smem_bytes = (2 * BM * SLD + 2 * BN * SLD + 256 + 512 + 128) * 4;  // 114176
    cudaFuncSetAttribute(gemm_min_kernel<false>,
                         cudaFuncAttributeMaxDynamicSharedMemorySize, smem_bytes);
    cudaFuncSetAttribute(gemm_min_kernel<true>,
                         cudaFuncAttributeMaxDynamicSharedMemorySize, smem_bytes);

    // fp16 conversions + exact center norms
    int n4x = BATCH * KDIM / 4;
    conv_x_kernel<<<n4x / 256, 256>>>(x, n4x);
    int n4c = NCLS * KDIM / 4;
    conv_c_kernel<<<(n4c + 255) / 256, 256>>>(centers, n4c);
    c2_kernel<<<NCLS, 256>>>(centers);

    // main GEMM: x vs centers (grid.x = n-tiles so same-M tiles are adjacent -> L2 reuse of A)
    gemm_min_kernel<false><<<dim3(NT, BATCH / BM), 256, smem_bytes>>>(labels);

    // centers vs centers
    gemm_min_kernel<true><<<dim3(NT, NPAD / BM), 256, smem_bytes>>>(labels);

    // reduction chain
    cen_kernel<<<4, 256>>>();
    partial_kernel<<<64, 256>>>(labels);
    finish_kernel<<<1, 32>>>(out);
}

// round 7
// speedup vs baseline: 1.2211x; 1.2211x over previous
#include <cuda_runtime.h>
#include <cuda_fp16.h>
#include <cstdint>

// Problem constants
#define BATCH   16384
#define NCLS    1000
#define NPAD    1024
#define KDIM    1024

// GEMM tiling (fp16) — round-5 proven shape: CTA 128x128, 8 warps 4(M)x2(N)
#define BM 128
#define BN 128
#define BKH 64               // halves per k-chunk (128 bytes per smem row)
#define KT (KDIM / BKH)      // 16 k-chunks
#define NT 8                 // 8 * 128 = 1024 >= 1000
#define SLD 36               // smem row stride in uint32 (32 data + 4 pad)

// ---------------------------------------------------------------------------
// Scratch (zero-initialized; pad rows of g_ch stay zero forever)
// ---------------------------------------------------------------------------
__device__ __half g_xh[(size_t)BATCH * KDIM];    // fp16 x
__device__ __half g_ch[(size_t)NPAD * KDIM];     // fp16 centers, rows 1000..1023 zero
__device__ float  g_c2[NPAD];                    // exact fp32 ||c||^2
__device__ float  g_pos[BATCH];
__device__ float  g_minxc[(size_t)BATCH * NT];
__device__ float  g_mincc[(size_t)NPAD * NT];
__device__ float  g_cen[NPAD];
__device__ float  g_part[64];

// ---------------------------------------------------------------------------
// Prep: fp32 -> fp16 (RN). Device symbols referenced only in device code.
// ---------------------------------------------------------------------------
__device__ __forceinline__ uint2 cvt4(float4 v) {
    __half2 lo = __floats2half2_rn(v.x, v.y);
    __half2 hi = __floats2half2_rn(v.z, v.w);
    uint2 o;
    o.x = *reinterpret_cast<uint32_t*>(&lo);
    o.y = *reinterpret_cast<uint32_t*>(&hi);
    return o;
}

__global__ void conv_x_kernel(const float* __restrict__ src, int n4) {
    int i = blockIdx.x * blockDim.x + threadIdx.x;
    if (i < n4)
        reinterpret_cast<uint2*>(g_xh)[i] = cvt4(reinterpret_cast<const float4*>(src)[i]);
}

__global__ void conv_c_kernel(const float* __restrict__ src, int n4) {
    int i = blockIdx.x * blockDim.x + threadIdx.x;
    if (i < n4)
        reinterpret_cast<uint2*>(g_ch)[i] = cvt4(reinterpret_cast<const float4*>(src)[i]);
}

// Exact fp32 squared norms of centers
__global__ void c2_kernel(const float* __restrict__ centers) {
    int j = blockIdx.x;
    const float* row = centers + (size_t)j * KDIM;
    float acc = 0.f;
    for (int k = threadIdx.x; k < KDIM; k += 256) {
        float v = row[k];
        acc += v * v;
    }
    __shared__ float s[256];
    s[threadIdx.x] = acc;
    __syncthreads();
    for (int off = 128; off > 0; off >>= 1) {
        if (threadIdx.x < off) s[threadIdx.x] += s[threadIdx.x + off];
        __syncthreads();
    }
    if (threadIdx.x == 0) g_c2[j] = s[0];
}

// ---------------------------------------------------------------------------
// fp16 GEMM + fused min epilogue (round-5 structure, ldmatrix fragment loads)
// e[r,c] = 0.5*||c_c||^2 - dot(A_r, C_c)
// SELF=false: A = g_xh; exclude c == label[r]; write g_pos, g_minxc
// SELF=true:  A = g_ch; exclude c == r;        write g_mincc
// ---------------------------------------------------------------------------
__device__ __forceinline__ void cp_tile(const __half* gbase, uint32_t* sbase, int tid) {
#pragma unroll
    for (int i = 0; i < 4; i++) {
        int g = i * 256 + tid;          // 0..1023 chunk id
        int r = g >> 3;                 // row 0..127
        int q = g & 7;                  // 16B chunk within row
        uint32_t d = (uint32_t)__cvta_generic_to_shared(sbase + r * SLD + q * 4);
        const __half* s = gbase + (size_t)r * KDIM + q * 8;
        asm volatile("cp.async.cg.shared.global [%0], [%1], 16;" :: "r"(d), "l"(s));
    }
}

__device__ __forceinline__ void ldsm4(uint32_t& r0, uint32_t& r1, uint32_t& r2,
                                      uint32_t& r3, uint32_t addr) {
    asm volatile("ldmatrix.sync.aligned.m8n8.x4.shared.b16 {%0,%1,%2,%3}, [%4];"
                 : "=r"(r0), "=r"(r1), "=r"(r2), "=r"(r3) : "r"(addr));
}

template <bool SELF>
__global__ void __launch_bounds__(256)
gemm_min_kernel(const int* __restrict__ labels) {
    extern __shared__ uint32_t smem[];
    uint32_t* As  = smem;                         // 2 * 128 * 36 u32
    uint32_t* Bs  = smem + 2 * BM * SLD;          // 2 * 128 * 36 u32
    float*    c2s = (float*)(Bs + 2 * BN * SLD);  // 128 floats (pre-scaled by 0.5)
    float*    red = c2s + 128;                    // 128 * 2 floats
    int*      labs = (int*)(red + 256);           // 128 ints

    const int tid  = threadIdx.x;
    const int warp = tid >> 5;
    const int lane = tid & 31;
    const int wm   = warp >> 1;   // 0..3  (M warps, 32 rows each)
    const int wn   = warp & 1;    // 0..1  (N warps, 64 cols each)
    const int bx   = blockIdx.x;  // n-tile 0..7
    const int m0   = blockIdx.y * BM;
    const int n0   = bx * BN;

    const __half* A = SELF ? g_ch : g_xh;

    if (tid < 128) {
        c2s[tid] = 0.5f * g_c2[n0 + tid];
        if (!SELF) labs[tid] = labels[m0 + tid];
    }

    float acc[2][8][4];
#pragma unroll
    for (int mi = 0; mi < 2; mi++)
#pragma unroll
        for (int ni = 0; ni < 8; ni++)
#pragma unroll
            for (int r = 0; r < 4; r++) acc[mi][ni][r] = 0.f;

    const __half* Abase = A + (size_t)m0 * KDIM;
    const __half* Bbase = g_ch + (size_t)n0 * KDIM;

    // ldmatrix per-lane base addresses (byte units in shared space).
    // A: lanes 0-7 -> rows 0-7 k16B-off 0 (a0), 8-15 -> rows 8-15 off 0 (a1),
    //    16-23 -> rows 0-7 off 16B (a2), 24-31 -> rows 8-15 off 16B (a3)
    // B: lanes 0-7 -> n-rows 0-7 off 0 (b0,ni), 8-15 -> rows 0-7 off 16B (b1,ni),
    //    16-23 -> rows 8-15 off 0 (b0,ni+1), 24-31 -> rows 8-15 off 16B (b1,ni+1)
    const uint32_t smb = (uint32_t)__cvta_generic_to_shared(smem);
    const int rowA  = (lane & 7) + ((lane >> 3) & 1) * 8;
    const int koffA = (lane >> 4) * 4;                 // u32 units
    const int rowB  = (lane & 7) + ((lane >> 4) & 1) * 8;
    const int koffB = ((lane >> 3) & 1) * 4;           // u32 units

    uint32_t aAddr[2], bAddr[4];
#pragma unroll
    for (int mi = 0; mi < 2; mi++)
        aAddr[mi] = smb + 4u * ((wm * 32 + mi * 16 + rowA) * SLD + koffA);
#pragma unroll
    for (int pi = 0; pi < 4; pi++)
        bAddr[pi] = smb + 4u * (2 * BM * SLD + (wn * 64 + pi * 16 + rowB) * SLD + koffB);

    const uint32_t stA = BM * SLD * 4;   // stage stride bytes (A region)
    const uint32_t stB = BN * SLD * 4;   // stage stride bytes (B region)

    // prologue: stage 0
    cp_tile(Abase, As, tid);
    cp_tile(Bbase, Bs, tid);
    asm volatile("cp.async.commit_group;");

    const int lr = lane >> 2, lc = lane & 3;

    for (int kt = 0; kt < KT; kt++) {
        if (kt + 1 < KT) {
            int st = (kt + 1) & 1;
            cp_tile(Abase + (size_t)(kt + 1) * BKH, As + st * BM * SLD, tid);
            cp_tile(Bbase + (size_t)(kt + 1) * BKH, Bs + st * BN * SLD, tid);
            asm volatile("cp.async.commit_group;");
            asm volatile("cp.async.wait_group 1;");
        } else {
            asm volatile("cp.async.wait_group 0;");
        }
        __syncthreads();

        const uint32_t sA = (kt & 1) * stA;
        const uint32_t sB = (kt & 1) * stB;

#pragma unroll
        for (int kk = 0; kk < 4; kk++) {
            uint32_t af[2][4], bf[8][2];
#pragma unroll
            for (int mi = 0; mi < 2; mi++)
                ldsm4(af[mi][0], af[mi][1], af[mi][2], af[mi][3],
                      aAddr[mi] + sA + kk * 32);
#pragma unroll
            for (int pi = 0; pi < 4; pi++)
                ldsm4(bf[2 * pi][0], bf[2 * pi][1], bf[2 * pi + 1][0], bf[2 * pi + 1][1],
                      bAddr[pi] + sB + kk * 32);

#pragma unroll
            for (int mi = 0; mi < 2; mi++)
#pragma unroll
                for (int ni = 0; ni < 8; ni++) {
                    asm volatile(
                        "mma.sync.aligned.m16n8k16.row.col.f32.f16.f16.f32 "
                        "{%0,%1,%2,%3}, {%4,%5,%6,%7}, {%8,%9}, {%0,%1,%2,%3};"
                        : "+f"(acc[mi][ni][0]), "+f"(acc[mi][ni][1]),
                          "+f"(acc[mi][ni][2]), "+f"(acc[mi][ni][3])
                        : "r"(af[mi][0]), "r"(af[mi][1]), "r"(af[mi][2]), "r"(af[mi][3]),
                          "r"(bf[ni][0]), "r"(bf[ni][1]));
                }
        }
        __syncthreads();
    }

    // ---------------- fused epilogue (verbatim round 5) ----------------
    const float INF = __int_as_float(0x7f800000);
    float rmin[2][2];

#pragma unroll
    for (int mi = 0; mi < 2; mi++)
#pragma unroll
        for (int h = 0; h < 2; h++) {
            int rloc = wm * 32 + mi * 16 + lr + 8 * h;
            float rm = INF;
#pragma unroll
            for (int ni = 0; ni < 8; ni++)
#pragma unroll
                for (int cc = 0; cc < 2; cc++) {
                    int cloc = wn * 64 + ni * 8 + lc * 2 + cc;
                    float e = c2s[cloc] - acc[mi][ni][h * 2 + cc];
                    int cg = n0 + cloc;
                    bool excl = (cg >= NCLS);
                    if (SELF) {
                        excl = excl || (cg == m0 + rloc);
                    } else if (cg == labs[rloc]) {
                        g_pos[m0 + rloc] = e;
                        excl = true;
                    }
                    if (!excl) rm = fminf(rm, e);
                }
            rmin[mi][h] = rm;
        }

#pragma unroll
    for (int mi = 0; mi < 2; mi++)
#pragma unroll
        for (int h = 0; h < 2; h++) {
            float v = rmin[mi][h];
            v = fminf(v, __shfl_xor_sync(0xffffffffu, v, 1));
            v = fminf(v, __shfl_xor_sync(0xffffffffu, v, 2));
            rmin[mi][h] = v;
        }

    if (lc == 0) {
#pragma unroll
        for (int mi = 0; mi < 2; mi++)
#pragma unroll
            for (int h = 0; h < 2; h++) {
                int rloc = wm * 32 + mi * 16 + lr + 8 * h;
                red[rloc * 2 + wn] = rmin[mi][h];
            }
    }
    __syncthreads();

    if (tid < 128) {
        float v = fminf(red[tid * 2], red[tid * 2 + 1]);
        int rg = m0 + tid;
        if (SELF) {
            if (rg < NCLS) g_mincc[(size_t)rg * NT + bx] = v;
        } else {
            g_minxc[(size_t)rg * NT + bx] = v;
        }
    }
}

// ---------------------------------------------------------------------------
// Deterministic reduction chain
// ---------------------------------------------------------------------------
__global__ void cen_kernel() {
    int j = blockIdx.x * blockDim.x + threadIdx.x;
    if (j < NCLS) {
        float4 a = reinterpret_cast<const float4*>(g_mincc)[j * 2];
        float4 b = reinterpret_cast<const float4*>(g_mincc)[j * 2 + 1];
        float m = fminf(fminf(fminf(a.x, a.y), fminf(a.z, a.w)),
                        fminf(fminf(b.x, b.y), fminf(b.z, b.w)));
        g_cen[j] = 0.5f * g_c2[j] + m;
    }
}

__global__ void partial_kernel(const int* __restrict__ labels) {
    int b = blockIdx.x * 256 + threadIdx.x;
    float4 a = reinterpret_cast<const float4*>(g_minxc)[b * 2];
    float4 c = reinterpret_cast<const float4*>(g_minxc)[b * 2 + 1];
    float m = fminf(fminf(fminf(a.x, a.y), fminf(a.z, a.w)),
                    fminf(fminf(c.x, c.y), fminf(c.z, c.w)));
    float t1 = g_pos[b] + 5.0f - m;     // 0.5||x||^2 cancels in pos - neg
    float t2 = 7.0f - g_cen[labels[b]];
    float v = fmaxf(t1, 0.f) + fmaxf(t2, 0.f);
    __shared__ float s[256];
    s[threadIdx.x] = v;
    __syncthreads();
    for (int off = 128; off > 0; off >>= 1) {
        if (threadIdx.x < off) s[threadIdx.x] += s[threadIdx.x + off];
        __syncthreads();
    }
    if (threadIdx.x == 0) g_part[blockIdx.x] = s[0];
}

__global__ void finish_kernel(float* __restrict__ out) {
    int t = threadIdx.x;   // 32 threads
    float v = g_part[t] + g_part[t + 32];
#pragma unroll
    for (int off = 16; off > 0; off >>= 1)
        v += __shfl_xor_sync(0xffffffffu, v, off);
    if (t == 0) out[0] = v * (1.0f / (float)BATCH);
}

// ---------------------------------------------------------------------------
// Launch
// ---------------------------------------------------------------------------
extern "C" void kernel_launch(void* const* d_in, const int* in_sizes, int n_in,
                              void* d_out, int out_size) {
    const float* x       = (const float*)d_in[0];
    const int*   labels  = (const int*)d_in[1];
    const float* centers = (const float*)d_in[2];
    float* out = (float*)d_out;

    const int smem_bytes = (2 * BM * SLD + 2 * BN * SLD + 128 + 256 + 128) * 4;  // 75776
    cudaFuncSetAttribute(gemm_min_kernel<false>,
                         cudaFuncAttributeMaxDynamicSharedMemorySize, smem_bytes);
    cudaFuncSetAttribute(gemm_min_kernel<true>,
                         cudaFuncAttributeMaxDynamicSharedMemorySize, smem_bytes);

    // fp16 conversions + exact center norms
    int n4x = BATCH * KDIM / 4;
    conv_x_kernel<<<n4x / 256, 256>>>(x, n4x);
    int n4c = NCLS * KDIM / 4;
    conv_c_kernel<<<(n4c + 255) / 256, 256>>>(centers, n4c);
    c2_kernel<<<NCLS, 256>>>(centers);

    // main GEMM: x vs centers
    gemm_min_kernel<false><<<dim3(NT, BATCH / BM), 256, smem_bytes>>>(labels);

    // centers vs centers
    gemm_min_kernel<true><<<dim3(NT, NPAD / BM), 256, smem_bytes>>>(labels);

    // reduction chain
    cen_kernel<<<4, 256>>>();
    partial_kernel<<<64, 256>>>(labels);
    finish_kernel<<<1, 32>>>(out);
}

// round 9
// speedup vs baseline: 1.2534x; 1.0265x over previous
#include <cuda_runtime.h>
#include <cuda_fp16.h>
#include <cstdint>

// Problem constants
#define BATCH   16384
#define NCLS    1000
#define NPAD    1024
#define KDIM    1024

// GEMM tiling (fp16): CTA 128x128, 8 warps 4(M)x2(N), 3-stage cp.async ring
#define BM 128
#define BN 128
#define BKH 64               // halves per k-chunk (128 bytes per smem row)
#define KT (KDIM / BKH)      // 16 k-chunks
#define NT 8                 // 8 * 128 = 1024 >= 1000
#define SLD 36               // smem row stride in uint32 (32 data + 4 pad)
#define NSTG 3
#define STG_U32 ((BM + BN) * SLD)      // u32 per stage (A then B)
#define MB (BATCH / BM)                 // 128 x-tiles in M
#define GRIDY (MB + NPAD / BM)          // 136 (last 8 rows = centers self-GEMM)

// ---------------------------------------------------------------------------
// Scratch (zero-initialized; pad rows of g_ch stay zero forever)
// ---------------------------------------------------------------------------
__device__ __half g_xh[(size_t)BATCH * KDIM];    // fp16 x
__device__ __half g_ch[(size_t)NPAD * KDIM];     // fp16 centers, rows 1000..1023 zero
__device__ float  g_c2[NPAD];                    // exact fp32 ||c||^2
__device__ float  g_pos[BATCH];
__device__ float  g_minxc[(size_t)BATCH * NT];
__device__ float  g_mincc[(size_t)NPAD * NT];
__device__ float  g_cen[NPAD];
__device__ float  g_part[64];

// ---------------------------------------------------------------------------
// Prep
// ---------------------------------------------------------------------------
__device__ __forceinline__ uint2 cvt4(float4 v) {
    __half2 lo = __floats2half2_rn(v.x, v.y);
    __half2 hi = __floats2half2_rn(v.z, v.w);
    uint2 o;
    o.x = *reinterpret_cast<uint32_t*>(&lo);
    o.y = *reinterpret_cast<uint32_t*>(&hi);
    return o;
}

__global__ void conv_x_kernel(const float* __restrict__ src, int n4) {
    int i = blockIdx.x * blockDim.x + threadIdx.x;
    if (i < n4)
        reinterpret_cast<uint2*>(g_xh)[i] = cvt4(reinterpret_cast<const float4*>(src)[i]);
}

// Fused: convert one center row to fp16 AND compute its exact fp32 norm
__global__ void conv_c2_kernel(const float* __restrict__ centers) {
    int j = blockIdx.x;                 // class 0..999
    const float* row = centers + (size_t)j * KDIM;
    float acc = 0.f;
    for (int k4 = threadIdx.x; k4 < KDIM / 4; k4 += 256) {
        float4 v = reinterpret_cast<const float4*>(row)[k4];
        acc += v.x * v.x + v.y * v.y + v.z * v.z + v.w * v.w;
        reinterpret_cast<uint2*>(g_ch + (size_t)j * KDIM)[k4] = cvt4(v);
    }
    __shared__ float s[256];
    s[threadIdx.x] = acc;
    __syncthreads();
    for (int off = 128; off > 0; off >>= 1) {
        if (threadIdx.x < off) s[threadIdx.x] += s[threadIdx.x + off];
        __syncthreads();
    }
    if (threadIdx.x == 0) g_c2[j] = s[0];
}

// ---------------------------------------------------------------------------
// fp16 GEMM + fused min epilogue (merged: grid.y < MB -> x rows, else centers)
// e[r,c] = 0.5*||c_c||^2 - dot(A_r, C_c)
// ---------------------------------------------------------------------------
__device__ __forceinline__ void cp_tile(const __half* gbase, uint32_t* sbase, int tid) {
#pragma unroll
    for (int i = 0; i < 4; i++) {
        int g = i * 256 + tid;          // 0..1023 chunk id
        int r = g >> 3;                 // row 0..127
        int q = g & 7;                  // 16B chunk within row
        uint32_t d = (uint32_t)__cvta_generic_to_shared(sbase + r * SLD + q * 4);
        const __half* s = gbase + (size_t)r * KDIM + q * 8;
        asm volatile("cp.async.cg.shared.global [%0], [%1], 16;" :: "r"(d), "l"(s));
    }
}

__device__ __forceinline__ void ldsm4(uint32_t& r0, uint32_t& r1, uint32_t& r2,
                                      uint32_t& r3, uint32_t addr) {
    asm volatile("ldmatrix.sync.aligned.m8n8.x4.shared.b16 {%0,%1,%2,%3}, [%4];"
                 : "=r"(r0), "=r"(r1), "=r"(r2), "=r"(r3) : "r"(addr));
}

__global__ void __launch_bounds__(256)
gemm_min_kernel(const int* __restrict__ labels) {
    extern __shared__ uint32_t smem[];
    float* c2s  = (float*)(smem + NSTG * STG_U32);   // 128 floats (pre-scaled by 0.5)
    float* red  = c2s + 128;                         // 128 * 2 floats
    int*   labs = (int*)(red + 256);                 // 128 ints

    const int tid  = threadIdx.x;
    const int warp = tid >> 5;
    const int lane = tid & 31;
    const int wm   = warp >> 1;   // 0..3  (M warps, 32 rows each)
    const int wn   = warp & 1;    // 0..1  (N warps, 64 cols each)
    const int bx   = blockIdx.x;  // n-tile 0..7
    const int by   = blockIdx.y;
    const bool self = by >= MB;            // uniform per block
    const int m0   = (self ? (by - MB) : by) * BM;
    const int n0   = bx * BN;

    if (tid < 128) {
        c2s[tid] = 0.5f * g_c2[n0 + tid];
        if (!self) labs[tid] = labels[m0 + tid];
    }

    float acc[2][8][4];
#pragma unroll
    for (int mi = 0; mi < 2; mi++)
#pragma unroll
        for (int ni = 0; ni < 8; ni++)
#pragma unroll
            for (int r = 0; r < 4; r++) acc[mi][ni][r] = 0.f;

    const __half* Abase = (self ? g_ch : g_xh) + (size_t)m0 * KDIM;
    const __half* Bbase = g_ch + (size_t)n0 * KDIM;

    // ldmatrix per-lane base addresses (byte units, offsets within a stage)
    const uint32_t smb = (uint32_t)__cvta_generic_to_shared(smem);
    const int rowA  = (lane & 7) + ((lane >> 3) & 1) * 8;
    const int koffA = (lane >> 4) * 4;                 // u32 units
    const int rowB  = (lane & 7) + ((lane >> 4) & 1) * 8;
    const int koffB = ((lane >> 3) & 1) * 4;           // u32 units

    uint32_t aAddr[2], bAddr[4];
#pragma unroll
    for (int mi = 0; mi < 2; mi++)
        aAddr[mi] = smb + 4u * ((wm * 32 + mi * 16 + rowA) * SLD + koffA);
#pragma unroll
    for (int pi = 0; pi < 4; pi++)
        bAddr[pi] = smb + 4u * (BM * SLD + (wn * 64 + pi * 16 + rowB) * SLD + koffB);

    // prologue: stages 0, 1 (chunks 0, 1)
#pragma unroll
    for (int s = 0; s < 2; s++) {
        uint32_t* st = smem + s * STG_U32;
        cp_tile(Abase + (size_t)s * BKH, st, tid);
        cp_tile(Bbase + (size_t)s * BKH, st + BM * SLD, tid);
        asm volatile("cp.async.commit_group;");
    }

    const int lr = lane >> 2, lc = lane & 3;

    for (int kt = 0; kt < KT; kt++) {
        // 1) own-thread completion of chunk kt (pending = {kt, kt+1})
        if (kt + 1 < KT) asm volatile("cp.async.wait_group 1;");
        else             asm volatile("cp.async.wait_group 0;");
        // 2) publish chunk kt to ALL threads; also: all warps are done with
        //    iteration kt-1, so refilling stage (kt+2)%3 (consumed at kt-1) is safe
        __syncthreads();
        // 3) refill
        if (kt + 2 < KT) {
            uint32_t* st = smem + ((kt + 2) % NSTG) * STG_U32;
            cp_tile(Abase + (size_t)(kt + 2) * BKH, st, tid);
            cp_tile(Bbase + (size_t)(kt + 2) * BKH, st + BM * SLD, tid);
            asm volatile("cp.async.commit_group;");
        }
        // 4) compute chunk kt from stage kt%3
        const uint32_t sOff = (uint32_t)((kt % NSTG) * STG_U32 * 4);

#pragma unroll
        for (int kk = 0; kk < 4; kk++) {
            uint32_t af[2][4], bf[8][2];
#pragma unroll
            for (int mi = 0; mi < 2; mi++)
                ldsm4(af[mi][0], af[mi][1], af[mi][2], af[mi][3],
                      aAddr[mi] + sOff + kk * 32);
#pragma unroll
            for (int pi = 0; pi < 4; pi++)
                ldsm4(bf[2 * pi][0], bf[2 * pi][1], bf[2 * pi + 1][0], bf[2 * pi + 1][1],
                      bAddr[pi] + sOff + kk * 32);

#pragma unroll
            for (int mi = 0; mi < 2; mi++)
#pragma unroll
                for (int ni = 0; ni < 8; ni++) {
                    asm volatile(
                        "mma.sync.aligned.m16n8k16.row.col.f32.f16.f16.f32 "
                        "{%0,%1,%2,%3}, {%4,%5,%6,%7}, {%8,%9}, {%0,%1,%2,%3};"
                        : "+f"(acc[mi][ni][0]), "+f"(acc[mi][ni][1]),
                          "+f"(acc[mi][ni][2]), "+f"(acc[mi][ni][3])
                        : "r"(af[mi][0]), "r"(af[mi][1]), "r"(af[mi][2]), "r"(af[mi][3]),
                          "r"(bf[ni][0]), "r"(bf[ni][1]));
                }
        }
    }
    __syncthreads();   // all warps done with last stage before red[] reuse

    // ---------------- fused epilogue ----------------
    const float INF = __int_as_float(0x7f800000);
    float rmin[2][2];

#pragma unroll
    for (int mi = 0; mi < 2; mi++)
#pragma unroll
        for (int h = 0; h < 2; h++) {
            int rloc = wm * 32 + mi * 16 + lr + 8 * h;
            float rm = INF;
#pragma unroll
            for (int ni = 0; ni < 8; ni++)
#pragma unroll
                for (int cc = 0; cc < 2; cc++) {
                    int cloc = wn * 64 + ni * 8 + lc * 2 + cc;
                    float e = c2s[cloc] - acc[mi][ni][h * 2 + cc];
                    int cg = n0 + cloc;
                    bool excl = (cg >= NCLS);
                    if (self) {
                        excl = excl || (cg == m0 + rloc);
                    } else if (cg == labs[rloc]) {
                        g_pos[m0 + rloc] = e;
                        excl = true;
                    }
                    if (!excl) rm = fminf(rm, e);
                }
            rmin[mi][h] = rm;
        }

#pragma unroll
    for (int mi = 0; mi < 2; mi++)
#pragma unroll
        for (int h = 0; h < 2; h++) {
            float v = rmin[mi][h];
            v = fminf(v, __shfl_xor_sync(0xffffffffu, v, 1));
            v = fminf(v, __shfl_xor_sync(0xffffffffu, v, 2));
            rmin[mi][h] = v;
        }

    if (lc == 0) {
#pragma unroll
        for (int mi = 0; mi < 2; mi++)
#pragma unroll
            for (int h = 0; h < 2; h++) {
                int rloc = wm * 32 + mi * 16 + lr + 8 * h;
                red[rloc * 2 + wn] = rmin[mi][h];
            }
    }
    __syncthreads();

    if (tid < 128) {
        float v = fminf(red[tid * 2], red[tid * 2 + 1]);
        int rg = m0 + tid;
        if (self) {
            if (rg < NCLS) g_mincc[(size_t)rg * NT + bx] = v;
        } else {
            g_minxc[(size_t)rg * NT + bx] = v;
        }
    }
}

// ---------------------------------------------------------------------------
// Deterministic reduction chain
// ---------------------------------------------------------------------------
__global__ void cen_kernel() {
    int j = blockIdx.x * blockDim.x + threadIdx.x;
    if (j < NCLS) {
        float4 a = reinterpret_cast<const float4*>(g_mincc)[j * 2];
        float4 b = reinterpret_cast<const float4*>(g_mincc)[j * 2 + 1];
        float m = fminf(fminf(fminf(a.x, a.y), fminf(a.z, a.w)),
                        fminf(fminf(b.x, b.y), fminf(b.z, b.w)));
        g_cen[j] = 0.5f * g_c2[j] + m;
    }
}

__global__ void partial_kernel(const int* __restrict__ labels) {
    int b = blockIdx.x * 256 + threadIdx.x;
    float4 a = reinterpret_cast<const float4*>(g_minxc)[b * 2];
    float4 c = reinterpret_cast<const float4*>(g_minxc)[b * 2 + 1];
    float m = fminf(fminf(fminf(a.x, a.y), fminf(a.z, a.w)),
                    fminf(fminf(c.x, c.y), fminf(c.z, c.w)));
    float t1 = g_pos[b] + 5.0f - m;     // 0.5||x||^2 cancels in pos - neg
    float t2 = 7.0f - g_cen[labels[b]];
    float v = fmaxf(t1, 0.f) + fmaxf(t2, 0.f);
    __shared__ float s[256];
    s[threadIdx.x] = v;
    __syncthreads();
    for (int off = 128; off > 0; off >>= 1) {
        if (threadIdx.x < off) s[threadIdx.x] += s[threadIdx.x + off];
        __syncthreads();
    }
    if (threadIdx.x == 0) g_part[blockIdx.x] = s[0];
}

__global__ void finish_kernel(float* __restrict__ out) {
    int t = threadIdx.x;   // 32 threads
    float v = g_part[t] + g_part[t + 32];
#pragma unroll
    for (int off = 16; off > 0; off >>= 1)
        v += __shfl_xor_sync(0xffffffffu, v, off);
    if (t == 0) out[0] = v * (1.0f / (float)BATCH);
}

// ---------------------------------------------------------------------------
// Launch
// ---------------------------------------------------------------------------
extern "C" void kernel_launch(void* const* d_in, const int* in_sizes, int n_in,
                              void* d_out, int out_size) {
    const float* x       = (const float*)d_in[0];
    const int*   labels  = (const int*)d_in[1];
    const float* centers = (const float*)d_in[2];
    float* out = (float*)d_out;

    const int smem_bytes = (NSTG * STG_U32 + 128 + 256 + 128) * 4;   // 112640
    cudaFuncSetAttribute(gemm_min_kernel,
                         cudaFuncAttributeMaxDynamicSharedMemorySize, smem_bytes);

    // fp16 conversions + exact center norms (fused for centers)
    int n4x = BATCH * KDIM / 4;
    conv_x_kernel<<<n4x / 256, 256>>>(x, n4x);
    conv_c2_kernel<<<NCLS, 256>>>(centers);

    // merged GEMM: x vs centers (grid.y < 128) + centers vs centers (grid.y >= 128)
    gemm_min_kernel<<<dim3(NT, GRIDY), 256, smem_bytes>>>(labels);

    // reduction chain
    cen_kernel<<<4, 256>>>();
    partial_kernel<<<64, 256>>>(labels);
    finish_kernel<<<1, 32>>>(out);
}